// round 6
// baseline (speedup 1.0000x reference)
#include <cuda_runtime.h>
#include <math.h>
#include <stdint.h>

#define N 2048
#define H 64
#define DIN 128

__device__ float g_dA[N];
__device__ float g_h[N*H];
__device__ float g_hn[N*H];
__device__ float g_hd[N*H];
__device__ float g_hsq[N];
__device__ unsigned long long g_cand[N*16];
__device__ int   g_idx[N*4];
__device__ float g_cval[N*4];
__device__ float g_dc[N];
__device__ float g_Z1s[N*2*H];
__device__ float g_Z1f[N*2*H];
__device__ float g_part[8*N*2*H];
__device__ float g_zf[N*H], g_zt[N*H], g_zcf[N*H], g_zct[N*H];
__device__ float g_Lcf[N*H], g_Lct[N*H];
__device__ float g_cs[2*H];
__device__ double g_G[128*128];
__device__ double g_M1[64*64];
__device__ double g_M2[64*64];

__device__ __forceinline__ float leaky_f(float v){ return v > 0.f ? v : 0.1f*v; }

__device__ __forceinline__ unsigned int fmap(float v){
  unsigned int u = __float_as_uint(v);
  return (u & 0x80000000u) ? ~u : (u | 0x80000000u);
}

__device__ __forceinline__ void top4_insert(unsigned long long* t, unsigned long long key){
  if (key > t[3]) {
    t[3] = key;
    unsigned long long tmp;
    if (t[3] > t[2]) { tmp = t[2]; t[2] = t[3]; t[3] = tmp; }
    if (t[2] > t[1]) { tmp = t[1]; t[1] = t[2]; t[2] = tmp; }
    if (t[1] > t[0]) { tmp = t[0]; t[0] = t[1]; t[1] = tmp; }
  }
}

__global__ __launch_bounds__(256) void k_rowsum(const float* __restrict__ A){
  int i = blockIdx.x;
  float s = 0.f;
  for (int j = threadIdx.x; j < N; j += 256) s += A[(size_t)i*N + j];
  __shared__ float sh[256];
  sh[threadIdx.x] = s; __syncthreads();
  for (int o = 128; o > 0; o >>= 1){
    if (threadIdx.x < o) sh[threadIdx.x] += sh[threadIdx.x + o];
    __syncthreads();
  }
  if (threadIdx.x == 0) g_dA[i] = rsqrtf(sh[0] + 1e-10f);
}

__global__ __launch_bounds__(256) void k_h(const float* __restrict__ x,
                                           const float* __restrict__ W1,
                                           const float* __restrict__ b1){
  __shared__ float Ws[64][129];
  __shared__ float xs[16][128];
  __shared__ float hs[16][65];
  __shared__ float ss[16];
  int tid = threadIdx.x;
  int base = blockIdx.x * 16;
  for (int e = tid; e < 64*128; e += 256) Ws[e>>7][e&127] = W1[e];
  for (int e = tid; e < 16*128; e += 256) xs[e>>7][e&127] = x[(size_t)base*128 + e];
  __syncthreads();
  int o = tid & 63, rg = tid >> 6;
  float hv[4];
  #pragma unroll
  for (int rr = 0; rr < 4; rr++){
    int rl = rg*4 + rr;
    float a = b1[o];
    #pragma unroll 16
    for (int d = 0; d < 128; d++) a = fmaf(Ws[o][d], xs[rl][d], a);
    hv[rr] = leaky_f(a);
    hs[rl][o] = hv[rr];
  }
  __syncthreads();
  if (tid < 16){
    float s = 0.f;
    #pragma unroll 8
    for (int d = 0; d < 64; d++) s = fmaf(hs[tid][d], hs[tid][d], s);
    ss[tid] = s;
    g_hsq[base + tid] = s;
  }
  __syncthreads();
  #pragma unroll
  for (int rr = 0; rr < 4; rr++){
    int rl = rg*4 + rr, row = base + rl;
    float rn = rsqrtf(ss[rl]);
    float v = hv[rr];
    g_h [row*64 + o] = v;
    g_hn[row*64 + o] = v*rn + 1e-10f;
    g_hd[row*64 + o] = v*g_dA[row];
  }
}

// heat top-4: gemm-style, 64 rows x 512 j per block, transposed operands
__global__ __launch_bounds__(256) void k_heat(){
  __shared__ __align__(16) float pool[8832];
  float* As  = pool;            // [d 64][row 64] pad 68
  float* Bs  = pool + 4352;     // [d 64][j 64] pad 68
  float* asq = pool + 8704;
  float* bsq = pool + 8768;
  int tid = threadIdx.x;
  int rowbase = blockIdx.x * 64;
  int jbase = blockIdx.y * 512;
  int r0 = (tid >> 4) * 4, c0 = (tid & 15) * 4;
  for (int e = tid; e < 4096; e += 256)
    As[(e&63)*68 + (e>>6)] = g_h[(rowbase + (e>>6))*64 + (e&63)];
  if (tid < 64) asq[tid] = g_hsq[rowbase + tid];
  __syncthreads();
  float asqr[4];
  #pragma unroll
  for (int i = 0; i < 4; i++) asqr[i] = asq[r0 + i];
  unsigned long long t[4][4];
  #pragma unroll
  for (int i = 0; i < 4; i++)
    #pragma unroll
    for (int q = 0; q < 4; q++) t[i][q] = 0ull;
  for (int tile = 0; tile < 8; tile++){
    int jc = jbase + tile*64;
    __syncthreads();
    for (int e = tid; e < 4096; e += 256)
      Bs[(e&63)*68 + (e>>6)] = g_h[(jc + (e>>6))*64 + (e&63)];
    if (tid < 64) bsq[tid] = g_hsq[jc + tid];
    __syncthreads();
    float acc[4][4];
    #pragma unroll
    for (int i = 0; i < 4; i++)
      #pragma unroll
      for (int j = 0; j < 4; j++) acc[i][j] = 0.f;
    #pragma unroll 8
    for (int kk = 0; kk < 64; kk++){
      float4 a4 = *(const float4*)&As[kk*68 + r0];
      float4 b4 = *(const float4*)&Bs[kk*68 + c0];
      float av[4] = {a4.x, a4.y, a4.z, a4.w};
      float bv[4] = {b4.x, b4.y, b4.z, b4.w};
      #pragma unroll
      for (int i = 0; i < 4; i++)
        #pragma unroll
        for (int j = 0; j < 4; j++)
          acc[i][j] = fmaf(av[i], bv[j], acc[i][j]);
    }
    float bsqr[4];
    #pragma unroll
    for (int j = 0; j < 4; j++) bsqr[j] = bsq[c0 + j];
    #pragma unroll
    for (int i = 0; i < 4; i++)
      #pragma unroll
      for (int j = 0; j < 4; j++){
        float dist = asqr[i] + bsqr[j] - 2.f*acc[i][j] + 6.4e-9f;
        int jg = jc + c0 + j;
        unsigned long long key = ((unsigned long long)fmap(-dist) << 32)
                               | (unsigned int)(2047 - jg);
        top4_insert(t[i], key);
      }
  }
  __syncthreads();
  unsigned long long* cand = (unsigned long long*)pool;  // alias, 64x64 ull = 32KB
  #pragma unroll
  for (int i = 0; i < 4; i++)
    #pragma unroll
    for (int q = 0; q < 4; q++)
      cand[(r0 + i)*64 + c0 + q] = t[i][q];
  __syncthreads();
  if (tid < 64){
    unsigned long long m[4] = {0ull,0ull,0ull,0ull};
    for (int e = 0; e < 64; e++) top4_insert(m, cand[tid*64 + e]);
    #pragma unroll
    for (int q = 0; q < 4; q++)
      g_cand[(rowbase + tid)*16 + blockIdx.y*4 + q] = m[q];
  }
}

// merge 16 candidates -> top4 idx, then cos-sim values + dc
__global__ __launch_bounds__(256) void k_cos(){
  int w = threadIdx.x >> 5;
  int lane = threadIdx.x & 31;
  int row = blockIdx.x * 8 + w;
  unsigned long long t[4] = {0ull,0ull,0ull,0ull};
  if (lane < 16) t[0] = g_cand[row*16 + lane];
  #pragma unroll
  for (int off = 8; off >= 1; off >>= 1){
    unsigned long long r0 = __shfl_down_sync(0xffffffffu, t[0], off);
    unsigned long long r1 = __shfl_down_sync(0xffffffffu, t[1], off);
    unsigned long long r2 = __shfl_down_sync(0xffffffffu, t[2], off);
    unsigned long long r3 = __shfl_down_sync(0xffffffffu, t[3], off);
    top4_insert(t, r0); top4_insert(t, r1);
    top4_insert(t, r2); top4_insert(t, r3);
  }
  int idx[4];
  #pragma unroll
  for (int q = 0; q < 4; q++){
    unsigned long long k = __shfl_sync(0xffffffffu, t[q], 0);
    idx[q] = 2047 - (int)(unsigned int)(k & 0xFFFFFFFFull);
  }
  if (lane == 0){
    #pragma unroll
    for (int q = 0; q < 4; q++) g_idx[row*4 + q] = idx[q];
  }
  float c[4];
  #pragma unroll
  for (int q = 0; q < 4; q++){
    int j = idx[q];
    float s = g_hn[row*64 + lane]      * g_hn[j*64 + lane]
            + g_hn[row*64 + 32 + lane] * g_hn[j*64 + 32 + lane];
    for (int o = 16; o > 0; o >>= 1) s += __shfl_down_sync(0xffffffffu, s, o);
    c[q] = s;
  }
  if (lane == 0){
    float rs = c[0] + c[1] + c[2] + c[3];
    g_dc[row] = rsqrtf(rs + 1e-10f);
    #pragma unroll
    for (int q = 0; q < 4; q++) g_cval[row*4 + q] = c[q];
  }
}

// split-K GEMM over A: part[s] = A[:, ks] @ B[ks, :]
template<int C>
__global__ __launch_bounds__(256) void k_gemmA(const float* __restrict__ A){
  constexpr int CPT = C / 16;
  __shared__ __align__(16) float As[32][68];      // transposed: [kk][row]
  __shared__ __align__(16) float Bs[32][C + 4];
  const float* __restrict__ B = (C == 64) ? (const float*)g_hd : (const float*)g_Z1s;
  int tid = threadIdx.x;
  int rowbase = blockIdx.x * 64;
  int kb0 = blockIdx.y * 256;
  int r0 = (tid >> 4) * 4, c0 = (tid & 15) * CPT;
  float acc[4][CPT];
  #pragma unroll
  for (int i = 0; i < 4; i++)
    #pragma unroll
    for (int j = 0; j < CPT; j++) acc[i][j] = 0.f;
  for (int kb = kb0; kb < kb0 + 256; kb += 32){
    __syncthreads();
    #pragma unroll
    for (int e = tid; e < 2048; e += 256)
      As[e & 31][e >> 5] = A[(size_t)(rowbase + (e>>5))*N + kb + (e & 31)];
    #pragma unroll
    for (int e = tid; e < 32*C; e += 256)
      Bs[e / C][e % C] = B[(kb + e/C)*C + (e % C)];
    __syncthreads();
    #pragma unroll 8
    for (int kk = 0; kk < 32; kk++){
      float4 a4 = *(const float4*)&As[kk][r0];
      float av[4] = {a4.x, a4.y, a4.z, a4.w};
      #pragma unroll
      for (int j4 = 0; j4 < CPT/4; j4++){
        float4 b4 = *(const float4*)&Bs[kk][c0 + j4*4];
        float bv[4] = {b4.x, b4.y, b4.z, b4.w};
        #pragma unroll
        for (int i = 0; i < 4; i++)
          #pragma unroll
          for (int j = 0; j < 4; j++)
            acc[i][j4*4 + j] = fmaf(av[i], bv[j], acc[i][j4*4 + j]);
      }
    }
  }
  float* dst = g_part + (size_t)blockIdx.y * N * C;
  #pragma unroll
  for (int i = 0; i < 4; i++)
    #pragma unroll
    for (int j = 0; j < CPT; j++)
      dst[(rowbase + r0 + i)*C + c0 + j] = acc[i][j];
}

__global__ __launch_bounds__(256) void k_z1t(const float* __restrict__ WT1, const float* __restrict__ bT1,
                                             const float* __restrict__ WC1, const float* __restrict__ bC1){
  __shared__ float Wa_[64][65], Wb_[64][65];
  __shared__ float ps[4][65];
  int tid = threadIdx.x; int sub = tid >> 6; int o = tid & 63;
  for (int e = tid; e < 64*64; e += 256){
    Wa_[e>>6][e&63] = WT1[e];
    Wb_[e>>6][e&63] = WC1[e];
  }
  int row = blockIdx.x*4 + sub;
  float p = 0.f;
  #pragma unroll
  for (int s = 0; s < 8; s++) p += g_part[(size_t)s*N*64 + row*64 + o];
  float da = g_dA[row];
  ps[sub][o] = da * p;
  __syncthreads();
  float a1 = bT1[o], a2 = bC1[o];
  #pragma unroll 16
  for (int d = 0; d < 64; d++){
    float m = ps[sub][d];
    a1 = fmaf(Wa_[o][d], m, a1);
    a2 = fmaf(Wb_[o][d], m, a2);
  }
  g_Z1s[row*128 + o]      = da * leaky_f(a1);
  g_Z1s[row*128 + 64 + o] = da * leaky_f(a2);
}

__global__ __launch_bounds__(256) void k_z2t(const float* __restrict__ WT2, const float* __restrict__ bT2,
                                             const float* __restrict__ WC2, const float* __restrict__ bC2){
  __shared__ float Wa_[64][65], Wb_[64][65];
  __shared__ float ps[4][130];
  __shared__ float red[4][64];
  int tid = threadIdx.x; int sub = tid >> 6; int o = tid & 63;
  for (int e = tid; e < 64*64; e += 256){
    Wa_[e>>6][e&63] = WT2[e];
    Wb_[e>>6][e&63] = WC2[e];
  }
  int row = blockIdx.x*4 + sub;
  float da = g_dA[row];
  float pA = 0.f, pB = 0.f;
  #pragma unroll
  for (int s = 0; s < 8; s++){
    pA += g_part[(size_t)s*N*128 + row*128 + o];
    pB += g_part[(size_t)s*N*128 + row*128 + 64 + o];
  }
  ps[sub][o]      = da * pA;
  ps[sub][64 + o] = da * pB;
  __syncthreads();
  float a1 = bT2[o], a2 = bC2[o];
  #pragma unroll 16
  for (int d = 0; d < 64; d++){
    a1 = fmaf(Wa_[o][d], ps[sub][d],      a1);
    a2 = fmaf(Wb_[o][d], ps[sub][64 + d], a2);
  }
  float zt  = leaky_f(a1);
  float zct = leaky_f(a2);
  g_zt [row*64 + o] = zt;
  g_zct[row*64 + o] = zct;
  red[sub][o] = zct*zct;
  __syncthreads();
  for (int off = 32; off > 0; off >>= 1){
    if (o < off) red[sub][o] += red[sub][o + off];
    __syncthreads();
  }
  float mn = sqrtf(red[sub][0] * 0.015625f) + 1e-10f;
  g_Lct[row*64 + o] = zct / mn;
}

__global__ __launch_bounds__(256) void k_z1f(const float* __restrict__ WF1, const float* __restrict__ bF1,
                                             const float* __restrict__ WC1, const float* __restrict__ bC1){
  __shared__ float Wa_[64][65], Wb_[64][65];
  __shared__ float ms[4][65];
  int tid = threadIdx.x; int sub = tid >> 6; int o = tid & 63;
  for (int e = tid; e < 64*64; e += 256){
    Wa_[e>>6][e&63] = WF1[e];
    Wb_[e>>6][e&63] = WC1[e];
  }
  int row = blockIdx.x*4 + sub;
  float dci = g_dc[row];
  float m = 0.f;
  #pragma unroll
  for (int t = 0; t < 4; t++){
    int j = g_idx[row*4 + t];
    float coef = g_cval[row*4 + t] * dci * g_dc[j];
    m = fmaf(coef, g_h[j*64 + o], m);
  }
  ms[sub][o] = m;
  __syncthreads();
  float a1 = bF1[o], a2 = bC1[o];
  #pragma unroll 16
  for (int d = 0; d < 64; d++){
    float v = ms[sub][d];
    a1 = fmaf(Wa_[o][d], v, a1);
    a2 = fmaf(Wb_[o][d], v, a2);
  }
  g_Z1f[row*128 + o]      = leaky_f(a1);
  g_Z1f[row*128 + 64 + o] = leaky_f(a2);
}

__global__ __launch_bounds__(256) void k_z2f(const float* __restrict__ WF2, const float* __restrict__ bF2,
                                             const float* __restrict__ WC2, const float* __restrict__ bC2){
  __shared__ float Wa_[64][65], Wb_[64][65];
  __shared__ float ms[4][130];
  __shared__ float red[4][64];
  int tid = threadIdx.x; int sub = tid >> 6; int o = tid & 63;
  for (int e = tid; e < 64*64; e += 256){
    Wa_[e>>6][e&63] = WF2[e];
    Wb_[e>>6][e&63] = WC2[e];
  }
  int row = blockIdx.x*4 + sub;
  float dci = g_dc[row];
  float mf = 0.f, mc = 0.f;
  #pragma unroll
  for (int t = 0; t < 4; t++){
    int j = g_idx[row*4 + t];
    float coef = g_cval[row*4 + t] * dci * g_dc[j];
    mf = fmaf(coef, g_Z1f[j*128 + o],      mf);
    mc = fmaf(coef, g_Z1f[j*128 + 64 + o], mc);
  }
  ms[sub][o]      = mf;
  ms[sub][64 + o] = mc;
  __syncthreads();
  float a1 = bF2[o], a2 = bC2[o];
  #pragma unroll 16
  for (int d = 0; d < 64; d++){
    a1 = fmaf(Wa_[o][d], ms[sub][d],      a1);
    a2 = fmaf(Wb_[o][d], ms[sub][64 + d], a2);
  }
  float zf  = leaky_f(a1);
  float zcf = leaky_f(a2);
  g_zf [row*64 + o] = zf;
  g_zcf[row*64 + o] = zcf;
  red[sub][o] = zcf*zcf;
  __syncthreads();
  for (int off = 32; off > 0; off >>= 1){
    if (o < off) red[sub][o] += red[sub][o + off];
    __syncthreads();
  }
  float mn = sqrtf(red[sub][0] * 0.015625f) + 1e-10f;
  g_Lcf[row*64 + o] = zcf / mn;
}

__global__ __launch_bounds__(256) void k_colmean(){
  int b = blockIdx.x;
  const float* src = (b < 64) ? g_zt : g_zf;
  int col = b & 63;
  float s = 0.f;
  for (int i = threadIdx.x; i < N; i += 256) s += src[i*64 + col];
  __shared__ float sh[256];
  sh[threadIdx.x] = s; __syncthreads();
  for (int o = 128; o > 0; o >>= 1){
    if (threadIdx.x < o) sh[threadIdx.x] += sh[threadIdx.x + o];
    __syncthreads();
  }
  if (threadIdx.x == 0) g_cs[b] = sh[0] / (float)N;
}

__global__ __launch_bounds__(256) void k_gram(int mode){
  const float *A0, *A1, *B0, *B1, *mean; double* out; int cb;
  if (mode == 0){ A0 = g_Lcf; A1 = g_Lct; B0 = g_Lcf; B1 = g_Lct; mean = 0; out = g_G; cb = 128; }
  else if (mode == 1){ A0 = g_zt; A1 = 0; B0 = g_zct; B1 = 0; mean = g_cs;      out = g_M1; cb = 64; }
  else              { A0 = g_zf; A1 = 0; B0 = g_zcf; B1 = 0; mean = g_cs + 64; out = g_M2; cb = 64; }
  int ci0 = blockIdx.x * 16, cj0 = blockIdx.y * 16;
  const float* Ap = (ci0 < 64) ? A0 : A1; int ca_off = ci0 & 63;
  const float* Bp = (cj0 < 64) ? B0 : B1; int cb_off = cj0 & 63;
  __shared__ float As[64][17], Bs[64][17];
  int tid = threadIdx.x;
  int ty = tid >> 4, tx = tid & 15;
  double acc = 0.0; float f = 0.f;
  for (int n0 = 0; n0 < N; n0 += 64){
    __syncthreads();
    #pragma unroll
    for (int e = tid; e < 1024; e += 256){
      int r = n0 + (e >> 4);
      float av = Ap[r*64 + ca_off + (e & 15)];
      if (mean) av -= mean[ca_off + (e & 15)];
      As[e >> 4][e & 15] = av;
      Bs[e >> 4][e & 15] = Bp[r*64 + cb_off + (e & 15)];
    }
    __syncthreads();
    #pragma unroll 16
    for (int r2 = 0; r2 < 64; r2++) f = fmaf(As[r2][ty], Bs[r2][tx], f);
    if (((n0 >> 6) & 1) == 1){ acc += (double)f; f = 0.f; }
  }
  out[(ci0 + ty)*cb + cj0 + tx] = acc;
}

__global__ __launch_bounds__(256) void k_att(const float* __restrict__ Wa, const float* __restrict__ ba,
                                             const float* __restrict__ q,  const float* __restrict__ W2,
                                             const float* __restrict__ b2, float* __restrict__ out){
  __shared__ float Was[64][65];
  __shared__ float qv[64];
  __shared__ float zsh[4][3][64];
  __shared__ float red[4][64];
  __shared__ float sv[4][3];
  __shared__ float av[4][3];
  __shared__ float zag[4][64];
  int tid = threadIdx.x; int sub = tid >> 6; int o = tid & 63;
  for (int e = tid; e < 64*64; e += 256) Was[e>>6][e&63] = Wa[e];
  if (tid < 64) qv[tid] = q[tid];
  __syncthreads();
  int row = blockIdx.x*4 + sub;
  float zfv  = g_zf [row*64 + o];
  float ztv  = g_zt [row*64 + o];
  float zcv  = 0.5f*(g_zcf[row*64 + o] + g_zct[row*64 + o]);
  zsh[sub][0][o] = zfv;
  zsh[sub][1][o] = ztv;
  zsh[sub][2][o] = zcv;
  __syncthreads();
  #pragma unroll
  for (int kk = 0; kk < 3; kk++){
    float t = ba[o];
    #pragma unroll 16
    for (int d = 0; d < 64; d++) t = fmaf(Was[o][d], zsh[sub][kk][d], t);
    t = tanhf(t) * qv[o];
    red[sub][o] = t;
    __syncthreads();
    if (o < 32) red[sub][o] += red[sub][o + 32];
    __syncthreads();
    if (o < 32){
      float s = red[sub][o];
      for (int off = 16; off > 0; off >>= 1) s += __shfl_down_sync(0xffffffffu, s, off);
      if (o == 0) sv[sub][kk] = s;
    }
    __syncthreads();
  }
  if (o == 0){
    float m = fmaxf(sv[sub][0], fmaxf(sv[sub][1], sv[sub][2]));
    float e0 = expf(sv[sub][0]-m), e1 = expf(sv[sub][1]-m), e2 = expf(sv[sub][2]-m);
    float inv = 1.f/(e0+e1+e2);
    av[sub][0] = e0*inv; av[sub][1] = e1*inv; av[sub][2] = e2*inv;
  }
  __syncthreads();
  zag[sub][o] = av[sub][0]*zfv + av[sub][1]*ztv + av[sub][2]*zcv;
  __syncthreads();
  if (o < 7){
    float v = b2[o];
    #pragma unroll 16
    for (int d = 0; d < 64; d++) v = fmaf(W2[o*64 + d], zag[sub][d], v);
    out[row*7 + o] = v;
  }
}

__global__ __launch_bounds__(256) void k_final(float* __restrict__ out){
  int tid = threadIdx.x;
  double lc = 0.0, ld = 0.0;
  for (int e = tid; e < 128*128; e += 256){
    int a = e >> 7, b = e & 127;
    double s = ((a < 64) == (b < 64)) ? 1.0 : -1.0;
    double g = g_G[e];
    lc += s * g * g;
  }
  for (int e = tid; e < 64*64; e += 256){
    double m1 = g_M1[e]; ld += m1*m1;
    double m2 = g_M2[e]; ld += m2*m2;
  }
  __shared__ double s1[256], s2[256];
  s1[tid] = lc; s2[tid] = ld; __syncthreads();
  for (int o = 128; o > 0; o >>= 1){
    if (tid < o){ s1[tid] += s1[tid + o]; s2[tid] += s2[tid + o]; }
    __syncthreads();
  }
  if (tid == 0){
    out[N*7]     = (float)(s1[0] / ((double)N * (double)N));
    out[N*7 + 1] = (float)(s2[0] / (2047.0 * 2047.0));
  }
}

extern "C" void kernel_launch(void* const* d_in, const int* in_sizes, int n_in,
                              void* d_out, int out_size){
  const float* x   = (const float*)d_in[0];
  const float* A   = (const float*)d_in[1];
  const float* W1  = (const float*)d_in[3];
  const float* b1  = (const float*)d_in[4];
  const float* WF1 = (const float*)d_in[5];
  const float* bF1 = (const float*)d_in[6];
  const float* WF2 = (const float*)d_in[7];
  const float* bF2 = (const float*)d_in[8];
  const float* WT1 = (const float*)d_in[9];
  const float* bT1 = (const float*)d_in[10];
  const float* WT2 = (const float*)d_in[11];
  const float* bT2 = (const float*)d_in[12];
  const float* WC1 = (const float*)d_in[13];
  const float* bC1 = (const float*)d_in[14];
  const float* WC2 = (const float*)d_in[15];
  const float* bC2 = (const float*)d_in[16];
  const float* Wa  = (const float*)d_in[17];
  const float* ba  = (const float*)d_in[18];
  const float* q   = (const float*)d_in[19];
  const float* W2  = (const float*)d_in[20];
  const float* b2  = (const float*)d_in[21];
  float* out = (float*)d_out;

  k_rowsum<<<N, 256>>>(A);
  k_h<<<N/16, 256>>>(x, W1, b1);
  k_heat<<<dim3(32, 4), 256>>>();
  k_cos<<<N/8, 256>>>();
  k_gemmA<64><<<dim3(32, 8), 256>>>(A);
  k_z1t<<<N/4, 256>>>(WT1, bT1, WC1, bC1);
  k_gemmA<128><<<dim3(32, 8), 256>>>(A);
  k_z2t<<<N/4, 256>>>(WT2, bT2, WC2, bC2);
  k_z1f<<<N/4, 256>>>(WF1, bF1, WC1, bC1);
  k_z2f<<<N/4, 256>>>(WF2, bF2, WC2, bC2);
  k_colmean<<<128, 256>>>();
  k_gram<<<dim3(8, 8), 256>>>(0);
  k_gram<<<dim3(4, 4), 256>>>(1);
  k_gram<<<dim3(4, 4), 256>>>(2);
  k_att<<<N/4, 256>>>(Wa, ba, q, W2, b2, out);
  k_final<<<1, 256>>>(out);
}

// round 7
// speedup vs baseline: 1.9698x; 1.9698x over previous
#include <cuda_runtime.h>
#include <math.h>
#include <stdint.h>

#define N 2048
#define H 64

typedef unsigned long long ull;

__device__ float g_dA[N];
__device__ float g_h[N*H];
__device__ float g_hn[N*H];
__device__ float g_hd[N*H];
__device__ float g_hsq[N];
__device__ ull   g_cand[N*16];
__device__ int   g_idx[N*4];
__device__ float g_cval[N*4];
__device__ float g_dc[N];
__device__ float g_Z1s[N*2*H];
__device__ float g_Z1f[N*2*H];
__device__ float g_part[8*N*2*H];
__device__ float g_zf[N*H], g_zt[N*H], g_zcf[N*H], g_zct[N*H];
__device__ float g_Lcf[N*H], g_Lct[N*H];
__device__ double g_G[128*128];
__device__ double g_M1[64*64];
__device__ double g_M2[64*64];

__device__ __forceinline__ float leaky_f(float v){ return v > 0.f ? v : 0.1f*v; }

__device__ __forceinline__ unsigned int fmap(float v){
  unsigned int u = __float_as_uint(v);
  return (u & 0x80000000u) ? ~u : (u | 0x80000000u);
}

__device__ __forceinline__ void top4_insert(ull* t, ull key){
  if (key > t[3]) {
    t[3] = key;
    ull tmp;
    if (t[3] > t[2]) { tmp = t[2]; t[2] = t[3]; t[3] = tmp; }
    if (t[2] > t[1]) { tmp = t[1]; t[1] = t[2]; t[2] = tmp; }
    if (t[1] > t[0]) { tmp = t[0]; t[0] = t[1]; t[1] = tmp; }
  }
}

__device__ __forceinline__ ull pk2(float lo, float hi){
  ull r;
  asm("mov.b64 %0, {%1, %2};" : "=l"(r) : "f"(lo), "f"(hi));
  return r;
}
__device__ __forceinline__ void upk2(ull v, float& lo, float& hi){
  asm("mov.b64 {%0, %1}, %2;" : "=f"(lo), "=f"(hi) : "l"(v));
}
__device__ __forceinline__ ull ffma2(ull a, ull b, ull c){
  ull r;
  asm("fma.rn.f32x2 %0, %1, %2, %3;" : "=l"(r) : "l"(a), "l"(b), "l"(c));
  return r;
}

// ============ 1. fused: rowsum(A) + h = leaky(x@W1^T+b1) + hn/hd/hsq ============
__global__ __launch_bounds__(256) void k_pre(const float* __restrict__ A,
                                             const float* __restrict__ x,
                                             const float* __restrict__ W1,
                                             const float* __restrict__ b1){
  __shared__ float Ws[64][129];
  __shared__ float xs[16][128];
  __shared__ float hs[16][65];
  __shared__ float ss[16];
  __shared__ float das[16];
  int tid = threadIdx.x;
  int base = blockIdx.x * 16;
  for (int e = tid; e < 64*128; e += 256) Ws[e>>7][e&127] = W1[e];
  for (int e = tid; e < 16*128; e += 256) xs[e>>7][e&127] = x[(size_t)base*128 + e];
  {
    int w = tid >> 5, lane = tid & 31;
    int r0 = base + w*2;
    const float* p0 = A + (size_t)r0*N;
    const float* p1 = p0 + N;
    float s0 = 0.f, s1 = 0.f;
    for (int i = lane; i < N; i += 32){ s0 += p0[i]; s1 += p1[i]; }
    for (int o = 16; o > 0; o >>= 1){
      s0 += __shfl_down_sync(0xffffffffu, s0, o);
      s1 += __shfl_down_sync(0xffffffffu, s1, o);
    }
    if (lane == 0){
      float d0 = rsqrtf(s0 + 1e-10f), d1 = rsqrtf(s1 + 1e-10f);
      das[w*2] = d0; das[w*2+1] = d1;
      g_dA[r0] = d0; g_dA[r0+1] = d1;
    }
  }
  __syncthreads();
  int o = tid & 63, rg = tid >> 6;
  float hv[4];
  #pragma unroll
  for (int rr = 0; rr < 4; rr++){
    int rl = rg*4 + rr;
    float a = b1[o];
    #pragma unroll 16
    for (int d = 0; d < 128; d++) a = fmaf(Ws[o][d], xs[rl][d], a);
    hv[rr] = leaky_f(a);
    hs[rl][o] = hv[rr];
  }
  __syncthreads();
  if (tid < 16){
    float s = 0.f;
    #pragma unroll 8
    for (int d = 0; d < 64; d++) s = fmaf(hs[tid][d], hs[tid][d], s);
    ss[tid] = s;
    g_hsq[base + tid] = s;
  }
  __syncthreads();
  #pragma unroll
  for (int rr = 0; rr < 4; rr++){
    int rl = rg*4 + rr, row = base + rl;
    float rn = rsqrtf(ss[rl]);
    float v = hv[rr];
    g_h [row*64 + o] = v;
    g_hn[row*64 + o] = v*rn + 1e-10f;
    g_hd[row*64 + o] = v*das[rl];
  }
}

// ============ shared role: split-K GEMM over A with FFMA2 ============
template<int C>
__device__ __forceinline__ void gemm_role(const float* __restrict__ A,
                                          const float* __restrict__ B,
                                          int rowblk, int ksplit, float* smem){
  constexpr int CPT = C / 16;
  float* As2 = smem;                 // [32][132] row-duplicated pairs
  float* Bs  = smem + 32*132;        // [32][C+4]
  int tid = threadIdx.x;
  int rowbase = rowblk * 64;
  int kb0 = ksplit * 256;
  int r0 = (tid >> 4) * 4, c0 = (tid & 15) * CPT;
  ull acc[4][CPT/2];
  #pragma unroll
  for (int i = 0; i < 4; i++)
    #pragma unroll
    for (int j = 0; j < CPT/2; j++) acc[i][j] = 0ull;
  for (int kb = kb0; kb < kb0 + 256; kb += 32){
    __syncthreads();
    #pragma unroll
    for (int e = tid; e < 2048; e += 256){
      int k = e & 31, r = e >> 5;
      float v = A[(size_t)(rowbase + r)*N + kb + k];
      *(ull*)&As2[k*132 + 2*r] = pk2(v, v);
    }
    #pragma unroll
    for (int e = tid; e < 32*C; e += 256)
      Bs[(e / C)*(C+4) + (e % C)] = B[(kb + e/C)*C + (e % C)];
    __syncthreads();
    #pragma unroll 8
    for (int kk = 0; kk < 32; kk++){
      ulonglong2 av0 = *(const ulonglong2*)&As2[kk*132 + 2*r0];
      ulonglong2 av1 = *(const ulonglong2*)&As2[kk*132 + 2*r0 + 4];
      ull a[4] = {av0.x, av0.y, av1.x, av1.y};
      #pragma unroll
      for (int j4 = 0; j4 < CPT/4; j4++){
        ulonglong2 bv = *(const ulonglong2*)&Bs[kk*(C+4) + c0 + j4*4];
        #pragma unroll
        for (int i = 0; i < 4; i++){
          acc[i][j4*2]   = ffma2(a[i], bv.x, acc[i][j4*2]);
          acc[i][j4*2+1] = ffma2(a[i], bv.y, acc[i][j4*2+1]);
        }
      }
    }
  }
  float* dst = g_part + (size_t)ksplit * N * C;
  #pragma unroll
  for (int i = 0; i < 4; i++)
    #pragma unroll
    for (int j = 0; j < CPT/2; j++){
      float lo, hi;
      upk2(acc[i][j], lo, hi);
      dst[(rowbase + r0 + i)*C + c0 + 2*j]     = lo;
      dst[(rowbase + r0 + i)*C + c0 + 2*j + 1] = hi;
    }
}

// ============ 2. stage1: heat-top4 (256 blocks) || gemmA<64> (256 blocks) ============
__global__ __launch_bounds__(256) void k_stage1(const float* __restrict__ A){
  __shared__ __align__(16) float smem[8800];
  int b = blockIdx.x, tid = threadIdx.x;
  if (b < 256){
    float* As2 = smem;              // [64][68] dup pairs (32 rows)
    float* Bs  = smem + 64*68;      // [64][68]
    float* asq = smem + 2*64*68;    // 32
    float* bsq = asq + 32;          // 64
    int rowbase = (b & 63) * 32;
    int jsplit  = b >> 6;
    int jbase   = jsplit * 512;
    int r0 = (tid >> 4) * 2, c0 = (tid & 15) * 4;
    for (int e = tid; e < 32*64; e += 256){
      int r = e >> 6, d = e & 63;
      float v = g_h[(rowbase + r)*64 + d];
      *(ull*)&As2[d*68 + 2*r] = pk2(v, v);
    }
    if (tid < 32) asq[tid] = g_hsq[rowbase + tid];
    __syncthreads();
    float asqr0 = asq[r0], asqr1 = asq[r0+1];
    ull t[2][4];
    #pragma unroll
    for (int i = 0; i < 2; i++)
      #pragma unroll
      for (int q = 0; q < 4; q++) t[i][q] = 0ull;
    for (int tile = 0; tile < 8; tile++){
      int jc = jbase + tile*64;
      __syncthreads();
      for (int e = tid; e < 4096; e += 256)
        Bs[(e & 63)*68 + (e >> 6)] = g_h[(jc + (e >> 6))*64 + (e & 63)];
      if (tid < 64) bsq[tid] = g_hsq[jc + tid];
      __syncthreads();
      ull acc[2][2] = {{0ull,0ull},{0ull,0ull}};
      #pragma unroll 8
      for (int kk = 0; kk < 64; kk++){
        ulonglong2 av = *(const ulonglong2*)&As2[kk*68 + 2*r0];
        ulonglong2 bv = *(const ulonglong2*)&Bs[kk*68 + c0];
        acc[0][0] = ffma2(av.x, bv.x, acc[0][0]);
        acc[0][1] = ffma2(av.x, bv.y, acc[0][1]);
        acc[1][0] = ffma2(av.y, bv.x, acc[1][0]);
        acc[1][1] = ffma2(av.y, bv.y, acc[1][1]);
      }
      float bq[4] = {bsq[c0], bsq[c0+1], bsq[c0+2], bsq[c0+3]};
      #pragma unroll
      for (int i = 0; i < 2; i++){
        float asqr = i ? asqr1 : asqr0;
        float d0, d1, d2, d3;
        upk2(acc[i][0], d0, d1);
        upk2(acc[i][1], d2, d3);
        float dd[4] = {d0, d1, d2, d3};
        #pragma unroll
        for (int j = 0; j < 4; j++){
          float dist = asqr + bq[j] - 2.f*dd[j] + 6.4e-9f;
          int jg = jc + c0 + j;
          ull key = ((ull)fmap(-dist) << 32) | (unsigned int)(2047 - jg);
          top4_insert(t[i], key);
        }
      }
    }
    __syncthreads();
    ull* cand = (ull*)smem;   // 32*64 ull = 16KB, aliases As2/Bs (done)
    #pragma unroll
    for (int i = 0; i < 2; i++)
      #pragma unroll
      for (int q = 0; q < 4; q++)
        cand[(r0 + i)*64 + c0 + q] = t[i][q];
    __syncthreads();
    if (tid < 32){
      ull m[4] = {0ull,0ull,0ull,0ull};
      for (int e = 0; e < 64; e++) top4_insert(m, cand[tid*64 + e]);
      #pragma unroll
      for (int q = 0; q < 4; q++)
        g_cand[(rowbase + tid)*16 + jsplit*4 + q] = m[q];
    }
  } else {
    int bb = b - 256;
    gemm_role<64>(A, g_hd, bb & 31, bb >> 5, smem);
  }
}

// ============ z-layer roles ============
__device__ __forceinline__ void z1t_role(int row4, const float* __restrict__ WT1, const float* __restrict__ bT1,
                                         const float* __restrict__ WC1, const float* __restrict__ bC1, float* smem){
  float* Wa_ = smem;            // 64x65
  float* Wb_ = smem + 4160;     // 64x65
  float* ps  = smem + 8320;     // 4x65
  int tid = threadIdx.x; int sub = tid >> 6; int o = tid & 63;
  for (int e = tid; e < 4096; e += 256){
    Wa_[(e>>6)*65 + (e&63)] = WT1[e];
    Wb_[(e>>6)*65 + (e&63)] = WC1[e];
  }
  int row = row4*4 + sub;
  float p = 0.f;
  #pragma unroll
  for (int s = 0; s < 8; s++) p += g_part[(size_t)s*N*64 + row*64 + o];
  float da = g_dA[row];
  ps[sub*65 + o] = da * p;
  __syncthreads();
  float a1 = bT1[o], a2 = bC1[o];
  #pragma unroll 16
  for (int d = 0; d < 64; d++){
    float m = ps[sub*65 + d];
    a1 = fmaf(Wa_[o*65 + d], m, a1);
    a2 = fmaf(Wb_[o*65 + d], m, a2);
  }
  g_Z1s[row*128 + o]      = da * leaky_f(a1);
  g_Z1s[row*128 + 64 + o] = da * leaky_f(a2);
}

__device__ __forceinline__ void cos_role(int blk){
  int w = threadIdx.x >> 5;
  int lane = threadIdx.x & 31;
  int row = blk * 8 + w;
  ull t[4] = {0ull,0ull,0ull,0ull};
  if (lane < 16) t[0] = g_cand[row*16 + lane];
  #pragma unroll
  for (int off = 8; off >= 1; off >>= 1){
    ull r0 = __shfl_down_sync(0xffffffffu, t[0], off);
    ull r1 = __shfl_down_sync(0xffffffffu, t[1], off);
    ull r2 = __shfl_down_sync(0xffffffffu, t[2], off);
    ull r3 = __shfl_down_sync(0xffffffffu, t[3], off);
    top4_insert(t, r0); top4_insert(t, r1);
    top4_insert(t, r2); top4_insert(t, r3);
  }
  int idx[4];
  #pragma unroll
  for (int q = 0; q < 4; q++){
    ull k = __shfl_sync(0xffffffffu, t[q], 0);
    idx[q] = 2047 - (int)(unsigned int)(k & 0xFFFFFFFFull);
  }
  if (lane == 0){
    #pragma unroll
    for (int q = 0; q < 4; q++) g_idx[row*4 + q] = idx[q];
  }
  float c[4];
  #pragma unroll
  for (int q = 0; q < 4; q++){
    int j = idx[q];
    float s = g_hn[row*64 + lane]      * g_hn[j*64 + lane]
            + g_hn[row*64 + 32 + lane] * g_hn[j*64 + 32 + lane];
    for (int o = 16; o > 0; o >>= 1) s += __shfl_down_sync(0xffffffffu, s, o);
    c[q] = s;
  }
  if (lane == 0){
    float rs = c[0] + c[1] + c[2] + c[3];
    g_dc[row] = rsqrtf(rs + 1e-10f);
    #pragma unroll
    for (int q = 0; q < 4; q++) g_cval[row*4 + q] = c[q];
  }
}

// ============ 3. stage2: cos (256) || z1t (512) ============
__global__ __launch_bounds__(256) void k_stage2(const float* __restrict__ WT1, const float* __restrict__ bT1,
                                                const float* __restrict__ WC1, const float* __restrict__ bC1){
  __shared__ __align__(16) float smem[8580];
  int b = blockIdx.x;
  if (b < 256) cos_role(b);
  else z1t_role(b - 256, WT1, bT1, WC1, bC1, smem);
}

__device__ __forceinline__ void z1f_role(int row4, const float* __restrict__ WF1, const float* __restrict__ bF1,
                                         const float* __restrict__ WC1, const float* __restrict__ bC1, float* smem){
  float* Wa_ = smem;
  float* Wb_ = smem + 4160;
  float* ms  = smem + 8320;   // 4x65
  int tid = threadIdx.x; int sub = tid >> 6; int o = tid & 63;
  for (int e = tid; e < 4096; e += 256){
    Wa_[(e>>6)*65 + (e&63)] = WF1[e];
    Wb_[(e>>6)*65 + (e&63)] = WC1[e];
  }
  int row = row4*4 + sub;
  float dci = g_dc[row];
  float m = 0.f;
  #pragma unroll
  for (int t = 0; t < 4; t++){
    int j = g_idx[row*4 + t];
    float coef = g_cval[row*4 + t] * dci * g_dc[j];
    m = fmaf(coef, g_h[j*64 + o], m);
  }
  ms[sub*65 + o] = m;
  __syncthreads();
  float a1 = bF1[o], a2 = bC1[o];
  #pragma unroll 16
  for (int d = 0; d < 64; d++){
    float v = ms[sub*65 + d];
    a1 = fmaf(Wa_[o*65 + d], v, a1);
    a2 = fmaf(Wb_[o*65 + d], v, a2);
  }
  g_Z1f[row*128 + o]      = leaky_f(a1);
  g_Z1f[row*128 + 64 + o] = leaky_f(a2);
}

// ============ 4. stage3: gemmA<128> (256) || z1f (512) ============
__global__ __launch_bounds__(256) void k_stage3(const float* __restrict__ A,
                                                const float* __restrict__ WF1, const float* __restrict__ bF1,
                                                const float* __restrict__ WC1, const float* __restrict__ bC1){
  __shared__ __align__(16) float smem[8608];
  int b = blockIdx.x;
  if (b < 256) gemm_role<128>(A, g_Z1s, b & 31, b >> 5, smem);
  else z1f_role(b - 256, WF1, bF1, WC1, bC1, smem);
}

__device__ __forceinline__ void z2t_role(int row4, const float* __restrict__ WT2, const float* __restrict__ bT2,
                                         const float* __restrict__ WC2, const float* __restrict__ bC2, float* smem){
  float* Wa_ = smem;
  float* Wb_ = smem + 4160;
  float* ps  = smem + 8320;   // 4x130
  float* red = smem + 8840;   // 4x64
  int tid = threadIdx.x; int sub = tid >> 6; int o = tid & 63;
  for (int e = tid; e < 4096; e += 256){
    Wa_[(e>>6)*65 + (e&63)] = WT2[e];
    Wb_[(e>>6)*65 + (e&63)] = WC2[e];
  }
  int row = row4*4 + sub;
  float da = g_dA[row];
  float pA = 0.f, pB = 0.f;
  #pragma unroll
  for (int s = 0; s < 8; s++){
    pA += g_part[(size_t)s*N*128 + row*128 + o];
    pB += g_part[(size_t)s*N*128 + row*128 + 64 + o];
  }
  ps[sub*130 + o]      = da * pA;
  ps[sub*130 + 64 + o] = da * pB;
  __syncthreads();
  float a1 = bT2[o], a2 = bC2[o];
  #pragma unroll 16
  for (int d = 0; d < 64; d++){
    a1 = fmaf(Wa_[o*65 + d], ps[sub*130 + d],      a1);
    a2 = fmaf(Wb_[o*65 + d], ps[sub*130 + 64 + d], a2);
  }
  float zt  = leaky_f(a1);
  float zct = leaky_f(a2);
  g_zt [row*64 + o] = zt;
  g_zct[row*64 + o] = zct;
  red[sub*64 + o] = zct*zct;
  __syncthreads();
  for (int off = 32; off > 0; off >>= 1){
    if (o < off) red[sub*64 + o] += red[sub*64 + o + off];
    __syncthreads();
  }
  float mn = sqrtf(red[sub*64] * 0.015625f) + 1e-10f;
  g_Lct[row*64 + o] = zct / mn;
}

__device__ __forceinline__ void z2f_role(int row4, const float* __restrict__ WF2, const float* __restrict__ bF2,
                                         const float* __restrict__ WC2, const float* __restrict__ bC2, float* smem){
  float* Wa_ = smem;
  float* Wb_ = smem + 4160;
  float* ms  = smem + 8320;   // 4x130
  float* red = smem + 8840;   // 4x64
  int tid = threadIdx.x; int sub = tid >> 6; int o = tid & 63;
  for (int e = tid; e < 4096; e += 256){
    Wa_[(e>>6)*65 + (e&63)] = WF2[e];
    Wb_[(e>>6)*65 + (e&63)] = WC2[e];
  }
  int row = row4*4 + sub;
  float dci = g_dc[row];
  float mf = 0.f, mc = 0.f;
  #pragma unroll
  for (int t = 0; t < 4; t++){
    int j = g_idx[row*4 + t];
    float coef = g_cval[row*4 + t] * dci * g_dc[j];
    mf = fmaf(coef, g_Z1f[j*128 + o],      mf);
    mc = fmaf(coef, g_Z1f[j*128 + 64 + o], mc);
  }
  ms[sub*130 + o]      = mf;
  ms[sub*130 + 64 + o] = mc;
  __syncthreads();
  float a1 = bF2[o], a2 = bC2[o];
  #pragma unroll 16
  for (int d = 0; d < 64; d++){
    a1 = fmaf(Wa_[o*65 + d], ms[sub*130 + d],      a1);
    a2 = fmaf(Wb_[o*65 + d], ms[sub*130 + 64 + d], a2);
  }
  float zf  = leaky_f(a1);
  float zcf = leaky_f(a2);
  g_zf [row*64 + o] = zf;
  g_zcf[row*64 + o] = zcf;
  red[sub*64 + o] = zcf*zcf;
  __syncthreads();
  for (int off = 32; off > 0; off >>= 1){
    if (o < off) red[sub*64 + o] += red[sub*64 + o + off];
    __syncthreads();
  }
  float mn = sqrtf(red[sub*64] * 0.015625f) + 1e-10f;
  g_Lcf[row*64 + o] = zcf / mn;
}

// ============ 5. stage4: z2t (512) || z2f (512) ============
__global__ __launch_bounds__(256) void k_stage4(const float* __restrict__ WT2, const float* __restrict__ bT2,
                                                const float* __restrict__ WF2, const float* __restrict__ bF2,
                                                const float* __restrict__ WC2, const float* __restrict__ bC2){
  __shared__ __align__(16) float smem[9096];
  int b = blockIdx.x;
  if (b < 512) z2t_role(b, WT2, bT2, WC2, bC2, smem);
  else z2f_role(b - 512, WF2, bF2, WC2, bC2, smem);
}

// ============ gram role (inline column means for modes 1/2) ============
__device__ __forceinline__ void gram_role(int mode, int bx, int by, float* smem){
  float* As = smem;            // 64x17
  float* Bs = smem + 1088;     // 64x17
  float* mean = smem + 2176;   // 16
  const float *A0, *A1, *B0, *B1; double* out; int cb; int use_mean;
  if (mode == 0){ A0 = g_Lcf; A1 = g_Lct; B0 = g_Lcf; B1 = g_Lct; use_mean = 0; out = g_G; cb = 128; }
  else if (mode == 1){ A0 = g_zt; A1 = 0; B0 = g_zct; B1 = 0; use_mean = 1; out = g_M1; cb = 64; }
  else              { A0 = g_zf; A1 = 0; B0 = g_zcf; B1 = 0; use_mean = 1; out = g_M2; cb = 64; }
  int ci0 = bx * 16, cj0 = by * 16;
  const float* Ap = (ci0 < 64) ? A0 : A1; int ca_off = ci0 & 63;
  const float* Bp = (cj0 < 64) ? B0 : B1; int cb_off = cj0 & 63;
  int tid = threadIdx.x;
  int ty = tid >> 4, tx = tid & 15;
  if (use_mean){
    float s = 0.f;
    for (int r = ty; r < N; r += 16) s += Ap[r*64 + ca_off + tx];
    As[ty*17 + tx] = s;
    __syncthreads();
    if (ty == 0){
      float m = 0.f;
      #pragma unroll
      for (int k = 0; k < 16; k++) m += As[k*17 + tx];
      mean[tx] = m / (float)N;
    }
    __syncthreads();
  }
  double acc = 0.0; float f = 0.f;
  for (int n0 = 0; n0 < N; n0 += 64){
    __syncthreads();
    #pragma unroll
    for (int e = tid; e < 1024; e += 256){
      int r = n0 + (e >> 4);
      float av = Ap[r*64 + ca_off + (e & 15)];
      if (use_mean) av -= mean[e & 15];
      As[(e >> 4)*17 + (e & 15)] = av;
      Bs[(e >> 4)*17 + (e & 15)] = Bp[r*64 + cb_off + (e & 15)];
    }
    __syncthreads();
    #pragma unroll 16
    for (int r2 = 0; r2 < 64; r2++) f = fmaf(As[r2*17 + ty], Bs[r2*17 + tx], f);
    if (((n0 >> 6) & 1) == 1){ acc += (double)f; f = 0.f; }
  }
  out[(ci0 + ty)*cb + cj0 + tx] = acc;
}

__device__ __forceinline__ void att_role(int blk, const float* __restrict__ Wa, const float* __restrict__ ba,
                                         const float* __restrict__ q,  const float* __restrict__ W2,
                                         const float* __restrict__ b2, float* __restrict__ out, float* smem){
  float* Was = smem;            // 64x65
  float* qv  = smem + 4160;     // 64
  float* zsh = smem + 4224;     // 4x3x64
  float* red = smem + 4992;     // 4x64
  float* sv  = smem + 5248;     // 4x3
  float* av  = smem + 5260;     // 4x3
  float* zag = smem + 5272;     // 4x64
  int tid = threadIdx.x; int sub = tid >> 6; int o = tid & 63;
  for (int e = tid; e < 4096; e += 256) Was[(e>>6)*65 + (e&63)] = Wa[e];
  if (tid < 64) qv[tid] = q[tid];
  __syncthreads();
  int row = blk*4 + sub;
  float zfv  = g_zf [row*64 + o];
  float ztv  = g_zt [row*64 + o];
  float zcv  = 0.5f*(g_zcf[row*64 + o] + g_zct[row*64 + o]);
  zsh[(sub*3 + 0)*64 + o] = zfv;
  zsh[(sub*3 + 1)*64 + o] = ztv;
  zsh[(sub*3 + 2)*64 + o] = zcv;
  __syncthreads();
  #pragma unroll
  for (int kk = 0; kk < 3; kk++){
    float t = ba[o];
    #pragma unroll 16
    for (int d = 0; d < 64; d++) t = fmaf(Was[o*65 + d], zsh[(sub*3 + kk)*64 + d], t);
    t = tanhf(t) * qv[o];
    red[sub*64 + o] = t;
    __syncthreads();
    if (o < 32) red[sub*64 + o] += red[sub*64 + o + 32];
    __syncthreads();
    if (o < 32){
      float s = red[sub*64 + o];
      for (int off = 16; off > 0; off >>= 1) s += __shfl_down_sync(0xffffffffu, s, off);
      if (o == 0) sv[sub*3 + kk] = s;
    }
    __syncthreads();
  }
  if (o == 0){
    float m = fmaxf(sv[sub*3], fmaxf(sv[sub*3+1], sv[sub*3+2]));
    float e0 = expf(sv[sub*3]-m), e1 = expf(sv[sub*3+1]-m), e2 = expf(sv[sub*3+2]-m);
    float inv = 1.f/(e0+e1+e2);
    av[sub*3] = e0*inv; av[sub*3+1] = e1*inv; av[sub*3+2] = e2*inv;
  }
  __syncthreads();
  zag[sub*64 + o] = av[sub*3]*zfv + av[sub*3+1]*ztv + av[sub*3+2]*zcv;
  __syncthreads();
  if (o < 7){
    float v = b2[o];
    #pragma unroll 16
    for (int d = 0; d < 64; d++) v = fmaf(W2[o*64 + d], zag[sub*64 + d], v);
    out[row*7 + o] = v;
  }
}

// ============ 6. stage5: gram x3 (96) || att (512) ============
__global__ __launch_bounds__(256) void k_stage5(const float* __restrict__ Wa, const float* __restrict__ ba,
                                                const float* __restrict__ q,  const float* __restrict__ W2,
                                                const float* __restrict__ b2, float* __restrict__ out){
  __shared__ __align__(16) float smem[5536];
  int b = blockIdx.x;
  if (b < 64)       gram_role(0, b >> 3, b & 7, smem);
  else if (b < 80)  gram_role(1, (b - 64) >> 2, (b - 64) & 3, smem);
  else if (b < 96)  gram_role(2, (b - 80) >> 2, (b - 80) & 3, smem);
  else              att_role(b - 96, Wa, ba, q, W2, b2, out, smem);
}

// ============ 7. final scalars ============
__global__ __launch_bounds__(256) void k_final(float* __restrict__ out){
  int tid = threadIdx.x;
  double lc = 0.0, ld = 0.0;
  for (int e = tid; e < 128*128; e += 256){
    int a = e >> 7, b = e & 127;
    double s = ((a < 64) == (b < 64)) ? 1.0 : -1.0;
    double g = g_G[e];
    lc += s * g * g;
  }
  for (int e = tid; e < 64*64; e += 256){
    double m1 = g_M1[e]; ld += m1*m1;
    double m2 = g_M2[e]; ld += m2*m2;
  }
  __shared__ double s1[256], s2[256];
  s1[tid] = lc; s2[tid] = ld; __syncthreads();
  for (int o = 128; o > 0; o >>= 1){
    if (tid < o){ s1[tid] += s1[tid + o]; s2[tid] += s2[tid + o]; }
    __syncthreads();
  }
  if (tid == 0){
    out[N*7]     = (float)(s1[0] / ((double)N * (double)N));
    out[N*7 + 1] = (float)(s2[0] / (2047.0 * 2047.0));
  }
}

extern "C" void kernel_launch(void* const* d_in, const int* in_sizes, int n_in,
                              void* d_out, int out_size){
  const float* x   = (const float*)d_in[0];
  const float* A   = (const float*)d_in[1];
  const float* W1  = (const float*)d_in[3];
  const float* b1  = (const float*)d_in[4];
  const float* WF1 = (const float*)d_in[5];
  const float* bF1 = (const float*)d_in[6];
  const float* WF2 = (const float*)d_in[7];
  const float* bF2 = (const float*)d_in[8];
  const float* WT1 = (const float*)d_in[9];
  const float* bT1 = (const float*)d_in[10];
  const float* WT2 = (const float*)d_in[11];
  const float* bT2 = (const float*)d_in[12];
  const float* WC1 = (const float*)d_in[13];
  const float* bC1 = (const float*)d_in[14];
  const float* WC2 = (const float*)d_in[15];
  const float* bC2 = (const float*)d_in[16];
  const float* Wa  = (const float*)d_in[17];
  const float* ba  = (const float*)d_in[18];
  const float* q   = (const float*)d_in[19];
  const float* W2  = (const float*)d_in[20];
  const float* b2  = (const float*)d_in[21];
  float* out = (float*)d_out;

  k_pre   <<<N/16, 256>>>(A, x, W1, b1);
  k_stage1<<<512,  256>>>(A);
  k_stage2<<<768,  256>>>(WT1, bT1, WC1, bC1);
  k_stage3<<<768,  256>>>(A, WF1, bF1, WC1, bC1);
  k_stage4<<<1024, 256>>>(WT2, bT2, WF2, bF2, WC2, bC2);
  k_stage5<<<608,  256>>>(Wa, ba, q, W2, b2, out);
  k_final <<<1,    256>>>(out);
}